// round 11
// baseline (speedup 1.0000x reference)
#include <cuda_runtime.h>
#include <cstdint>
#include <cstddef>

#define BB 32
#define NN 2048
#define DD 128
#define HH 128

// Scratch for q/k/v activations (allocation-free rule: static device arrays).
// g_v is reused as fp16x2 j-pair-packed storage (uint32 words [B*1024][128]).
__device__ float g_q[BB * NN * HH];
__device__ float g_k[BB * NN * HH];
__device__ float g_v[BB * NN * HH];

// ---------- packed f32x2 helpers (projection kernel) ----------
__device__ __forceinline__ unsigned long long pk2(float lo, float hi) {
    unsigned long long r;
    asm("mov.b64 %0, {%1, %2};" : "=l"(r) : "f"(lo), "f"(hi));
    return r;
}
__device__ __forceinline__ float2 upk2(unsigned long long p) {
    float2 f;
    asm("mov.b64 {%0, %1}, %2;" : "=f"(f.x), "=f"(f.y) : "l"(p));
    return f;
}
__device__ __forceinline__ unsigned long long f2fma(unsigned long long a,
                                                    unsigned long long b,
                                                    unsigned long long c) {
    unsigned long long d;
    asm("fma.rn.f32x2 %0, %1, %2, %3;" : "=l"(d) : "l"(a), "l"(b), "l"(c));
    return d;
}

__device__ __forceinline__ uint32_t tf32r(float x) {
    uint32_t r;
    asm("cvt.rna.tf32.f32 %0, %1;" : "=r"(r) : "f"(x));
    return r;
}
// pack two fp32 -> fp16x2 (lo = a, hi = b), saturating to finite
__device__ __forceinline__ uint32_t h2pack(float a, float b) {
    uint32_t r;
    asm("cvt.rn.satfinite.f16x2.f32 %0, %1, %2;" : "=r"(r) : "f"(b), "f"(a));
    return r;
}

// warp mma: D(16x8) += A(16x8,row,tf32) * B(8x8,col,tf32), fp32 accum
__device__ __forceinline__ void mma16n8k8(float* c, const uint32_t* a,
                                          uint32_t b0, uint32_t b1) {
    asm volatile(
        "mma.sync.aligned.m16n8k8.row.col.f32.tf32.tf32.f32 "
        "{%0,%1,%2,%3}, {%4,%5,%6,%7}, {%8,%9}, {%0,%1,%2,%3};"
        : "+f"(c[0]), "+f"(c[1]), "+f"(c[2]), "+f"(c[3])
        : "r"(a[0]), "r"(a[1]), "r"(a[2]), "r"(a[3]), "r"(b0), "r"(b1));
}
// warp mma: D(16x8) += A(16x16,row,f16) * B(16x8,col,f16), fp32 accum
__device__ __forceinline__ void mma16n8k16h(float* c, const uint32_t* a,
                                            uint32_t b0, uint32_t b1) {
    asm volatile(
        "mma.sync.aligned.m16n8k16.row.col.f32.f16.f16.f32 "
        "{%0,%1,%2,%3}, {%4,%5,%6,%7}, {%8,%9}, {%0,%1,%2,%3};"
        : "+f"(c[0]), "+f"(c[1]), "+f"(c[2]), "+f"(c[3])
        : "r"(a[0]), "r"(a[1]), "r"(a[2]), "r"(a[3]), "r"(b0), "r"(b1));
}

__device__ __forceinline__ uint32_t smem_u32(const void* p) {
    uint32_t a;
    asm("{ .reg .u64 t; cvta.to.shared.u64 t, %1; cvt.u32.u64 %0, t; }"
        : "=r"(a) : "l"(p));
    return a;
}

#define CP_ASYNC16(dst, src)                                                \
    asm volatile("cp.async.cg.shared.global [%0], [%1], 16;" ::             \
                     "r"(dst), "l"(src) : "memory")
#define CP_COMMIT() asm volatile("cp.async.commit_group;" ::: "memory")
#define CP_WAIT0() asm volatile("cp.async.wait_group 0;" ::: "memory")

// ============================================================
// Kernel A: fused QKV projection, out = tanh(x @ W + b)  (FFMA2)
// q,k: tf32-pre-rounded, h-dim permuted within 8-groups (cc -> (cc&3)*2+(cc>>2)).
// v: fp16x2 j-pair-packed: word[jp][h] = (v[2jp][h], v[2jp+1][h]), h natural.
// ============================================================
__global__ __launch_bounds__(256, 1) void proj_kernel(
    const float* __restrict__ x,
    const float* __restrict__ Wq, const float* __restrict__ bq,
    const float* __restrict__ Wk, const float* __restrict__ bk,
    const float* __restrict__ Wv, const float* __restrict__ bv) {
    extern __shared__ float sm[];
    float* xs = sm;              // 64*128
    float* ws = sm + 64 * 128;   // 32*128

    const float* W;
    const float* bias;
    bool isV;
    float* outp;
    if (blockIdx.y == 0)      { W = Wq; bias = bq; outp = g_q; isV = false; }
    else if (blockIdx.y == 1) { W = Wk; bias = bk; outp = g_k; isV = false; }
    else                      { W = Wv; bias = bv; outp = g_v; isV = true; }

    const int tid = threadIdx.x;
    const int rowg = tid >> 4;
    const int colg = tid & 15;
    const int row0 = blockIdx.x * 64;

    {
        const float4* src = reinterpret_cast<const float4*>(x + (size_t)row0 * DD);
        float4* dst = reinterpret_cast<float4*>(xs);
#pragma unroll
        for (int t = 0; t < 8; t++) dst[tid + t * 256] = src[tid + t * 256];
    }

    unsigned long long acc[4][4];
#pragma unroll
    for (int r = 0; r < 4; r++)
#pragma unroll
        for (int c = 0; c < 4; c++) acc[r][c] = 0ull;

#pragma unroll 1
    for (int chunk = 0; chunk < 4; chunk++) {
        const int kk0 = chunk * 32;
        __syncthreads();
        {
            const float4* src = reinterpret_cast<const float4*>(W + (size_t)kk0 * HH);
            float4* dst = reinterpret_cast<float4*>(ws);
#pragma unroll
            for (int t = 0; t < 4; t++) dst[tid + t * 256] = src[tid + t * 256];
        }
        __syncthreads();

#pragma unroll 2
        for (int kkl = 0; kkl < 32; kkl++) {
            const int kk = kk0 + kkl;
            float xv[4];
#pragma unroll
            for (int r = 0; r < 4; r++) xv[r] = xs[(rowg * 4 + r) * DD + kk];
            float4 wa = *reinterpret_cast<const float4*>(ws + kkl * HH + colg * 4);
            float4 wb = *reinterpret_cast<const float4*>(ws + kkl * HH + 64 + colg * 4);
            unsigned long long wp[4];
            wp[0] = *reinterpret_cast<unsigned long long*>(&wa.x);
            wp[1] = *reinterpret_cast<unsigned long long*>(&wa.z);
            wp[2] = *reinterpret_cast<unsigned long long*>(&wb.x);
            wp[3] = *reinterpret_cast<unsigned long long*>(&wb.z);
#pragma unroll
            for (int r = 0; r < 4; r++) {
                unsigned long long xp = pk2(xv[r], xv[r]);
#pragma unroll
                for (int c = 0; c < 4; c++) acc[r][c] = f2fma(xp, wp[c], acc[r][c]);
            }
        }
    }

    float4 ba = *reinterpret_cast<const float4*>(bias + colg * 4);
    float4 bb = *reinterpret_cast<const float4*>(bias + 64 + colg * 4);

    float vall[4][8];
#pragma unroll
    for (int r = 0; r < 4; r++) {
        float2 a0 = upk2(acc[r][0]);
        float2 a1 = upk2(acc[r][1]);
        float2 a2 = upk2(acc[r][2]);
        float2 a3 = upk2(acc[r][3]);
        vall[r][0] = tanhf(a0.x + ba.x);
        vall[r][1] = tanhf(a0.y + ba.y);
        vall[r][2] = tanhf(a1.x + ba.z);
        vall[r][3] = tanhf(a1.y + ba.w);
        vall[r][4] = tanhf(a2.x + bb.x);
        vall[r][5] = tanhf(a2.y + bb.y);
        vall[r][6] = tanhf(a3.x + bb.z);
        vall[r][7] = tanhf(a3.y + bb.w);
    }

    if (!isV) {
        const bool oddc = (colg & 1);
        const int gbase = (colg >> 1) * 8 + (oddc ? 4 : 0);
#pragma unroll
        for (int r = 0; r < 4; r++) {
            float v[8];
#pragma unroll
            for (int i = 0; i < 8; i++)
                v[i] = __uint_as_float(tf32r(vall[r][i]));
            float p[8];
#pragma unroll
            for (int i = 0; i < 8; i++)
                p[i] = __shfl_xor_sync(0xffffffffu, v[i], 1);
            float4 lo, hi;
            if (!oddc) {
                lo.x = v[0]; lo.y = p[0]; lo.z = v[1]; lo.w = p[1];
                hi.x = v[4]; hi.y = p[4]; hi.z = v[5]; hi.w = p[5];
            } else {
                lo.x = p[2]; lo.y = v[2]; lo.z = p[3]; lo.w = v[3];
                hi.x = p[6]; hi.y = v[6]; hi.z = p[7]; hi.w = v[7];
            }
            float* orow = outp + (size_t)(row0 + rowg * 4 + r) * HH;
            *reinterpret_cast<float4*>(orow + gbase) = lo;
            *reinterpret_cast<float4*>(orow + 64 + gbase) = hi;
        }
    } else {
        uint32_t* v2 = reinterpret_cast<uint32_t*>(g_v);
#pragma unroll
        for (int rp = 0; rp < 2; rp++) {
            const size_t jp = (size_t)(row0 + rowg * 4) / 2 + rp;
            uint32_t wv[8];
#pragma unroll
            for (int i = 0; i < 8; i++)
                wv[i] = h2pack(vall[2 * rp][i], vall[2 * rp + 1][i]);
            uint4 lo, hi;
            lo.x = wv[0]; lo.y = wv[1]; lo.z = wv[2]; lo.w = wv[3];
            hi.x = wv[4]; hi.y = wv[5]; hi.z = wv[6]; hi.w = wv[7];
            uint32_t* orow = v2 + jp * HH;
            *reinterpret_cast<uint4*>(orow + colg * 4) = lo;
            *reinterpret_cast<uint4*>(orow + 64 + colg * 4) = hi;
        }
    }
}

// ============================================================
// Kernel B: flash attention v9 — warp-pair j-split, 512 threads.
//  - 16 warps/CTA, 1 CTA/SM (RF-exact @128 regs) -> still 4 warps/SMSP
//  - warp pair p shares i-rows [p*16, p*16+16); sub=w&1 owns j-half of
//    each 32-j stage => per-warp LDS bytes: Q 8K + K 8K + V 4K + mask 1K
//  - O and lsum pair-merged through smem at the end (one-time 8KB/pair)
//  - tf32 QK (m16n8k8) + fp16 PV (m16n8k16); exp(s-10); zero shfl in loop
// smem (words): Q[128][136] | K[32][136] | Vt 2x[16][136]
// ============================================================
#define LDW 136
#define KS_OFF (128 * LDW)
#define VT_OFF (KS_OFF + 32 * LDW)
#define VT_STRIDE (16 * LDW)
#define SMEM_ATT ((VT_OFF + 2 * VT_STRIDE) * 4)

__global__ __launch_bounds__(512, 1) void attn_mma(
    const float* __restrict__ mask, float* __restrict__ out) {
    extern __shared__ uint32_t smw[];
    uint32_t* Qs = smw;
    uint32_t* Ks = smw + KS_OFF;
    const uint32_t smb = smem_u32(smw);

    const int tid = threadIdx.x;
    const int lane = tid & 31;
    const int w = tid >> 5;
    const int p = w >> 1;       // pair id 0..7 -> i-rows p*16..
    const int sub = w & 1;      // j-half within each stage
    const int b = blockIdx.x >> 4;
    const int i0 = (blockIdx.x & 15) << 7;
    const int qp = lane >> 2;
    const int ql = lane & 3;
    const int r0 = p * 16 + qp;

    const float* qg = g_q + ((size_t)(b * NN) + i0) * HH;
    const float* kg = g_k + (size_t)(b * NN) * HH;
    const uint32_t* vg2 =
        reinterpret_cast<const uint32_t*>(g_v) + (size_t)b * 1024 * HH;

    // ---- prologue: stage Q + K0 + V0(buf0) ----
#pragma unroll
    for (int t = 0; t < 8; t++) {
        const int idx = tid + t * 512;       // 0..4095
        const int row = idx >> 5, c4 = idx & 31;
        CP_ASYNC16(smb + (uint32_t)(row * LDW + c4 * 4) * 4, qg + idx * 4);
    }
#pragma unroll
    for (int t = 0; t < 2; t++) {
        const int idx = tid + t * 512;       // 0..1023
        const int row = idx >> 5, c4 = idx & 31;
        CP_ASYNC16(smb + (uint32_t)(KS_OFF + row * LDW + c4 * 4) * 4,
                   kg + idx * 4);
    }
    {
        const int row = tid >> 5, c4 = tid & 31;  // 0..511
        CP_ASYNC16(smb + (uint32_t)(VT_OFF + row * LDW + c4 * 4) * 4,
                   vg2 + (size_t)row * HH + c4 * 4);
    }
    CP_COMMIT();

    float oa[16][4];
#pragma unroll
    for (int h = 0; h < 16; h++)
#pragma unroll
        for (int c = 0; c < 4; c++) oa[h][c] = 0.0f;
    float ls0 = 0.0f, ls1 = 0.0f;

    const float* mrow0 = mask + ((size_t)(b * NN) + i0 + r0) * NN + 2 * ql;
    const float* mrow1 = mrow0 + (size_t)8 * NN;

    const uint32_t* qbase = Qs + r0 * LDW + 2 * ql;

#pragma unroll 1
    for (int jt = 0; jt < 64; jt++) {
        const int j0 = jt << 5;
        CP_WAIT0();
        __syncthreads();   // stage jt (K + V buf jt&1) visible; prior reads done

        // ---- issue V copy for jt+1 into other buffer (fully hidden) ----
        if (jt < 63) {
            const uint32_t vdst = smb +
                (uint32_t)(VT_OFF + ((jt + 1) & 1) * VT_STRIDE) * 4;
            const uint32_t* vn = vg2 + (size_t)((jt + 1) * 16) * HH;
            const int row = tid >> 5, c4 = tid & 31;
            CP_ASYNC16(vdst + (uint32_t)(row * LDW + c4 * 4) * 4,
                       vn + (size_t)row * HH + c4 * 4);
            CP_COMMIT();
        }

        // ---- prefetch this warp's j-half mask (hidden behind QK) ----
        float2 mh0[2], mh1[2];
#pragma unroll
        for (int nbl = 0; nbl < 2; nbl++) {
            const int jcol = j0 + (sub * 2 + nbl) * 8;
            mh0[nbl] = __ldg(reinterpret_cast<const float2*>(mrow0 + jcol));
            mh1[nbl] = __ldg(reinterpret_cast<const float2*>(mrow1 + jcol));
        }

        // ---- S = Q K^T over this warp's 16 j (full k) ----
        float sf[2][4];
#pragma unroll
        for (int nbl = 0; nbl < 2; nbl++)
#pragma unroll
            for (int c = 0; c < 4; c++) sf[nbl][c] = 0.0f;

#pragma unroll
        for (int k = 0; k < 16; k++) {
            uint2 q0 = *reinterpret_cast<const uint2*>(qbase + k * 8);
            uint2 q1 = *reinterpret_cast<const uint2*>(qbase + k * 8 + 8 * LDW);
            uint32_t qa[4] = {q0.x, q1.x, q0.y, q1.y};
#pragma unroll
            for (int nbl = 0; nbl < 2; nbl++) {
                uint2 kb = *reinterpret_cast<const uint2*>(
                    Ks + ((sub * 2 + nbl) * 8 + qp) * LDW + k * 8 + 2 * ql);
                mma16n8k8(sf[nbl], qa, kb.x, kb.y);
            }
        }

        __syncthreads();   // all warps done reading Ks
        if (jt < 63) {
            const float* kn = kg + ((size_t)(j0 + 32)) * HH;
#pragma unroll
            for (int t = 0; t < 2; t++) {
                const int idx = tid + t * 512;
                const int row = idx >> 5, c4 = idx & 31;
                CP_ASYNC16(smb + (uint32_t)(KS_OFF + row * LDW + c4 * 4) * 4,
                           kn + idx * 4);
            }
            CP_COMMIT();
        }

        // ---- mask + exp(s-10) + fp16 pack + PV over own 16 j ----
        {
            float pE0 = (mh0[0].x != 0.0f) ? __expf(sf[0][0] - 10.0f) : 0.0f;
            float pE1 = (mh0[0].y != 0.0f) ? __expf(sf[0][1] - 10.0f) : 0.0f;
            float pE2 = (mh1[0].x != 0.0f) ? __expf(sf[0][2] - 10.0f) : 0.0f;
            float pE3 = (mh1[0].y != 0.0f) ? __expf(sf[0][3] - 10.0f) : 0.0f;
            float pO0 = (mh0[1].x != 0.0f) ? __expf(sf[1][0] - 10.0f) : 0.0f;
            float pO1 = (mh0[1].y != 0.0f) ? __expf(sf[1][1] - 10.0f) : 0.0f;
            float pO2 = (mh1[1].x != 0.0f) ? __expf(sf[1][2] - 10.0f) : 0.0f;
            float pO3 = (mh1[1].y != 0.0f) ? __expf(sf[1][3] - 10.0f) : 0.0f;
            ls0 += (pE0 + pE1) + (pO0 + pO1);
            ls1 += (pE2 + pE3) + (pO2 + pO3);
            uint32_t pa[4];
            pa[0] = h2pack(pE0, pE1);
            pa[1] = h2pack(pE2, pE3);
            pa[2] = h2pack(pO0, pO1);
            pa[3] = h2pack(pO2, pO3);

            const uint32_t* sVt = smw + VT_OFF + (jt & 1) * VT_STRIDE;
            const uint32_t* vb0 = sVt + (sub * 8 + ql) * LDW + qp;
            const uint32_t* vb1 = sVt + (sub * 8 + ql + 4) * LDW + qp;
#pragma unroll
            for (int h = 0; h < 16; h++) {
                mma16n8k16h(oa[h], pa, vb0[h * 8], vb1[h * 8]);
            }
        }
    }

    // ---- epilogue: quad-reduce, pair-merge O and lsum, store ----
    ls0 += __shfl_xor_sync(0xffffffffu, ls0, 1);
    ls0 += __shfl_xor_sync(0xffffffffu, ls0, 2);
    ls1 += __shfl_xor_sync(0xffffffffu, ls1, 1);
    ls1 += __shfl_xor_sync(0xffffffffu, ls1, 2);

    __syncthreads();   // main loop done; Q/K areas reusable
    float* Xf = reinterpret_cast<float*>(smw) + p * 2112;   // 16 rows x 132
    float* lsx = reinterpret_cast<float*>(smw + KS_OFF);
    if (sub == 1) {
#pragma unroll
        for (int h = 0; h < 16; h++) {
            float2 v0, v1;
            v0.x = oa[h][0]; v0.y = oa[h][1];
            v1.x = oa[h][2]; v1.y = oa[h][3];
            *reinterpret_cast<float2*>(Xf + qp * 132 + h * 8 + 2 * ql) = v0;
            *reinterpret_cast<float2*>(Xf + (qp + 8) * 132 + h * 8 + 2 * ql) = v1;
        }
        if (ql == 0) {
            lsx[p * 32 + qp] = ls0;
            lsx[p * 32 + 16 + qp] = ls1;
        }
    }
    __syncthreads();
    if (sub == 0) {
        ls0 += lsx[p * 32 + qp];
        ls1 += lsx[p * 32 + 16 + qp];
        const float inv0 = 1.0f / ls0;
        const float inv1 = 1.0f / ls1;
        float* orow0 = out + ((size_t)(b * NN) + i0 + r0) * HH + 2 * ql;
        float* orow1 = orow0 + (size_t)8 * HH;
#pragma unroll
        for (int h = 0; h < 16; h++) {
            float2 x0 = *reinterpret_cast<float2*>(Xf + qp * 132 + h * 8 + 2 * ql);
            float2 x1 =
                *reinterpret_cast<float2*>(Xf + (qp + 8) * 132 + h * 8 + 2 * ql);
            float2 v0, v1;
            v0.x = (oa[h][0] + x0.x) * inv0;
            v0.y = (oa[h][1] + x0.y) * inv0;
            v1.x = (oa[h][2] + x1.x) * inv1;
            v1.y = (oa[h][3] + x1.y) * inv1;
            *reinterpret_cast<float2*>(orow0 + h * 8) = v0;
            *reinterpret_cast<float2*>(orow1 + h * 8) = v1;
        }
    }
}

extern "C" void kernel_launch(void* const* d_in, const int* in_sizes, int n_in,
                              void* d_out, int out_size) {
    const float* x    = (const float*)d_in[0];
    const float* mask = (const float*)d_in[1];
    const float* Wv   = (const float*)d_in[2];
    const float* bv   = (const float*)d_in[3];
    const float* Wk   = (const float*)d_in[4];
    const float* bk   = (const float*)d_in[5];
    const float* Wq   = (const float*)d_in[6];
    const float* bq   = (const float*)d_in[7];
    float* out = (float*)d_out;

    cudaFuncSetAttribute(proj_kernel, cudaFuncAttributeMaxDynamicSharedMemorySize,
                         49152);
    cudaFuncSetAttribute(attn_mma, cudaFuncAttributeMaxDynamicSharedMemorySize,
                         SMEM_ATT);

    proj_kernel<<<dim3(1024, 3, 1), 256, 49152>>>(x, Wq, bq, Wk, bk, Wv, bv);
    attn_mma<<<512, 512, SMEM_ATT>>>(mask, out);
}

// round 12
// speedup vs baseline: 1.3768x; 1.3768x over previous
#include <cuda_runtime.h>
#include <cstdint>
#include <cstddef>

#define BB 32
#define NN 2048
#define DD 128
#define HH 128

// Scratch (allocation-free rule: static device arrays).
// g_q/g_k reused as fp16x2 h-pair-packed uint32 [B*N][64].
// g_v reused as fp16x2 j-pair-packed uint32 [B*1024][128].
__device__ float g_q[BB * NN * HH];
__device__ float g_k[BB * NN * HH];
__device__ float g_v[BB * NN * HH];

// ---------- packed f32x2 helpers (projection kernel) ----------
__device__ __forceinline__ unsigned long long pk2(float lo, float hi) {
    unsigned long long r;
    asm("mov.b64 %0, {%1, %2};" : "=l"(r) : "f"(lo), "f"(hi));
    return r;
}
__device__ __forceinline__ float2 upk2(unsigned long long p) {
    float2 f;
    asm("mov.b64 {%0, %1}, %2;" : "=f"(f.x), "=f"(f.y) : "l"(p));
    return f;
}
__device__ __forceinline__ unsigned long long f2fma(unsigned long long a,
                                                    unsigned long long b,
                                                    unsigned long long c) {
    unsigned long long d;
    asm("fma.rn.f32x2 %0, %1, %2, %3;" : "=l"(d) : "l"(a), "l"(b), "l"(c));
    return d;
}

// pack two fp32 -> fp16x2 (lo = a, hi = b), saturating to finite
__device__ __forceinline__ uint32_t h2pack(float a, float b) {
    uint32_t r;
    asm("cvt.rn.satfinite.f16x2.f32 %0, %1, %2;" : "=r"(r) : "f"(b), "f"(a));
    return r;
}

// warp mma: D(16x8) += A(16x16,row,f16) * B(16x8,col,f16), fp32 accum
__device__ __forceinline__ void mma16n8k16h(float* c, const uint32_t* a,
                                            uint32_t b0, uint32_t b1) {
    asm volatile(
        "mma.sync.aligned.m16n8k16.row.col.f32.f16.f16.f32 "
        "{%0,%1,%2,%3}, {%4,%5,%6,%7}, {%8,%9}, {%0,%1,%2,%3};"
        : "+f"(c[0]), "+f"(c[1]), "+f"(c[2]), "+f"(c[3])
        : "r"(a[0]), "r"(a[1]), "r"(a[2]), "r"(a[3]), "r"(b0), "r"(b1));
}

__device__ __forceinline__ uint32_t smem_u32(const void* p) {
    uint32_t a;
    asm("{ .reg .u64 t; cvta.to.shared.u64 t, %1; cvt.u32.u64 %0, t; }"
        : "=r"(a) : "l"(p));
    return a;
}

#define CP_ASYNC16(dst, src)                                                \
    asm volatile("cp.async.cg.shared.global [%0], [%1], 16;" ::             \
                     "r"(dst), "l"(src) : "memory")
#define CP_COMMIT() asm volatile("cp.async.commit_group;" ::: "memory")
#define CP_WAIT0() asm volatile("cp.async.wait_group 0;" ::: "memory")

// ============================================================
// Kernel A: fused QKV projection, out = tanh(x @ W + b)  (FFMA2)
// q,k: fp16x2 h-pair packed, natural h order: word[i][hp]=(v[2hp],v[2hp+1])
// v:   fp16x2 j-pair packed: word[jp][h] = (v[2jp][h], v[2jp+1][h])
// ============================================================
__global__ __launch_bounds__(256, 1) void proj_kernel(
    const float* __restrict__ x,
    const float* __restrict__ Wq, const float* __restrict__ bq,
    const float* __restrict__ Wk, const float* __restrict__ bk,
    const float* __restrict__ Wv, const float* __restrict__ bv) {
    extern __shared__ float sm[];
    float* xs = sm;              // 64*128
    float* ws = sm + 64 * 128;   // 32*128

    const float* W;
    const float* bias;
    bool isV;
    float* outp;
    if (blockIdx.y == 0)      { W = Wq; bias = bq; outp = g_q; isV = false; }
    else if (blockIdx.y == 1) { W = Wk; bias = bk; outp = g_k; isV = false; }
    else                      { W = Wv; bias = bv; outp = g_v; isV = true; }

    const int tid = threadIdx.x;
    const int rowg = tid >> 4;
    const int colg = tid & 15;
    const int row0 = blockIdx.x * 64;

    {
        const float4* src = reinterpret_cast<const float4*>(x + (size_t)row0 * DD);
        float4* dst = reinterpret_cast<float4*>(xs);
#pragma unroll
        for (int t = 0; t < 8; t++) dst[tid + t * 256] = src[tid + t * 256];
    }

    unsigned long long acc[4][4];
#pragma unroll
    for (int r = 0; r < 4; r++)
#pragma unroll
        for (int c = 0; c < 4; c++) acc[r][c] = 0ull;

#pragma unroll 1
    for (int chunk = 0; chunk < 4; chunk++) {
        const int kk0 = chunk * 32;
        __syncthreads();
        {
            const float4* src = reinterpret_cast<const float4*>(W + (size_t)kk0 * HH);
            float4* dst = reinterpret_cast<float4*>(ws);
#pragma unroll
            for (int t = 0; t < 4; t++) dst[tid + t * 256] = src[tid + t * 256];
        }
        __syncthreads();

#pragma unroll 2
        for (int kkl = 0; kkl < 32; kkl++) {
            const int kk = kk0 + kkl;
            float xv[4];
#pragma unroll
            for (int r = 0; r < 4; r++) xv[r] = xs[(rowg * 4 + r) * DD + kk];
            float4 wa = *reinterpret_cast<const float4*>(ws + kkl * HH + colg * 4);
            float4 wb = *reinterpret_cast<const float4*>(ws + kkl * HH + 64 + colg * 4);
            unsigned long long wp[4];
            wp[0] = *reinterpret_cast<unsigned long long*>(&wa.x);
            wp[1] = *reinterpret_cast<unsigned long long*>(&wa.z);
            wp[2] = *reinterpret_cast<unsigned long long*>(&wb.x);
            wp[3] = *reinterpret_cast<unsigned long long*>(&wb.z);
#pragma unroll
            for (int r = 0; r < 4; r++) {
                unsigned long long xp = pk2(xv[r], xv[r]);
#pragma unroll
                for (int c = 0; c < 4; c++) acc[r][c] = f2fma(xp, wp[c], acc[r][c]);
            }
        }
    }

    float4 ba = *reinterpret_cast<const float4*>(bias + colg * 4);
    float4 bb = *reinterpret_cast<const float4*>(bias + 64 + colg * 4);

    float vall[4][8];
#pragma unroll
    for (int r = 0; r < 4; r++) {
        float2 a0 = upk2(acc[r][0]);
        float2 a1 = upk2(acc[r][1]);
        float2 a2 = upk2(acc[r][2]);
        float2 a3 = upk2(acc[r][3]);
        vall[r][0] = tanhf(a0.x + ba.x);
        vall[r][1] = tanhf(a0.y + ba.y);
        vall[r][2] = tanhf(a1.x + ba.z);
        vall[r][3] = tanhf(a1.y + ba.w);
        vall[r][4] = tanhf(a2.x + bb.x);
        vall[r][5] = tanhf(a2.y + bb.y);
        vall[r][6] = tanhf(a3.x + bb.z);
        vall[r][7] = tanhf(a3.y + bb.w);
    }

    if (!isV) {
        // q,k: fp16x2 h-pair pack, natural order; 64 words per row.
        uint32_t* o2 = reinterpret_cast<uint32_t*>(outp);
#pragma unroll
        for (int r = 0; r < 4; r++) {
            uint32_t* orow = o2 + (size_t)(row0 + rowg * 4 + r) * 64;
            uint2 lo, hi;
            lo.x = h2pack(vall[r][0], vall[r][1]);   // hp = 2*colg
            lo.y = h2pack(vall[r][2], vall[r][3]);   // hp = 2*colg+1
            hi.x = h2pack(vall[r][4], vall[r][5]);   // hp = 32+2*colg
            hi.y = h2pack(vall[r][6], vall[r][7]);
            *reinterpret_cast<uint2*>(orow + 2 * colg) = lo;
            *reinterpret_cast<uint2*>(orow + 32 + 2 * colg) = hi;
        }
    } else {
        uint32_t* v2 = reinterpret_cast<uint32_t*>(g_v);
#pragma unroll
        for (int rp = 0; rp < 2; rp++) {
            const size_t jp = (size_t)(row0 + rowg * 4) / 2 + rp;
            uint32_t wv[8];
#pragma unroll
            for (int i = 0; i < 8; i++)
                wv[i] = h2pack(vall[2 * rp][i], vall[2 * rp + 1][i]);
            uint4 lo, hi;
            lo.x = wv[0]; lo.y = wv[1]; lo.z = wv[2]; lo.w = wv[3];
            hi.x = wv[4]; hi.y = wv[5]; hi.z = wv[6]; hi.w = wv[7];
            uint32_t* orow = v2 + jp * HH;
            *reinterpret_cast<uint4*>(orow + colg * 4) = lo;
            *reinterpret_cast<uint4*>(orow + 64 + colg * 4) = hi;
        }
    }
}

// ============================================================
// Kernel B: flash attention v10 — ALL-fp16 MMA (QK and PV m16n8k16).
//  - R10 structure: 256 thr, 2 CTAs/SM, j-stage 32, V double-buffered,
//    K single buffer copied right after QK sync.
//  - Q/K fp16x2 h-pair packed: Q/K smem bytes HALVED vs tf32;
//    QK MMA count halved. fp16 mantissa == tf32 mantissa -> same accuracy.
// smem (words): Qh[128][68] | Kh[32][68] | Vt 2x[16][136] = 60928 B
// ============================================================
#define QLDH 68
#define KS_OFF (128 * QLDH)
#define VT_OFF (KS_OFF + 32 * QLDH)
#define VT_STRIDE (16 * 136)
#define SMEM_ATT ((VT_OFF + 2 * VT_STRIDE) * 4)

__global__ __launch_bounds__(256, 2) void attn_mma(
    const float* __restrict__ mask, float* __restrict__ out) {
    extern __shared__ uint32_t smw[];
    uint32_t* Qh = smw;
    uint32_t* Kh = smw + KS_OFF;
    const uint32_t smb = smem_u32(smw);

    const int tid = threadIdx.x;
    const int lane = tid & 31;
    const int w = tid >> 5;
    const int b = blockIdx.x >> 4;
    const int i0 = (blockIdx.x & 15) << 7;
    const int qp = lane >> 2;
    const int ql = lane & 3;
    const int r0 = w * 16 + qp;

    const uint32_t* qg2 =
        reinterpret_cast<const uint32_t*>(g_q) + ((size_t)(b * NN) + i0) * 64;
    const uint32_t* kg2 =
        reinterpret_cast<const uint32_t*>(g_k) + (size_t)(b * NN) * 64;
    const uint32_t* vg2 =
        reinterpret_cast<const uint32_t*>(g_v) + (size_t)b * 1024 * HH;

    // ---- prologue: stage Q (once) + K0 + V0(buf0) ----
#pragma unroll
    for (int t = 0; t < 8; t++) {
        const int idx = tid + t * 256;       // 0..2047 chunks of 16B
        const int row = idx >> 4, c4 = idx & 15;
        CP_ASYNC16(smb + (uint32_t)(row * QLDH + c4 * 4) * 4,
                   qg2 + (size_t)row * 64 + c4 * 4);
    }
#pragma unroll
    for (int t = 0; t < 2; t++) {
        const int idx = tid + t * 256;       // 0..511
        const int row = idx >> 4, c4 = idx & 15;
        CP_ASYNC16(smb + (uint32_t)(KS_OFF + row * QLDH + c4 * 4) * 4,
                   kg2 + (size_t)row * 64 + c4 * 4);
    }
#pragma unroll
    for (int t = 0; t < 2; t++) {
        const int idx = tid + t * 256;       // 0..511
        const int row = idx >> 5, c4 = idx & 31;
        CP_ASYNC16(smb + (uint32_t)(VT_OFF + row * 136 + c4 * 4) * 4,
                   vg2 + (size_t)row * HH + c4 * 4);
    }
    CP_COMMIT();

    float oa[16][4];
#pragma unroll
    for (int h = 0; h < 16; h++)
#pragma unroll
        for (int c = 0; c < 4; c++) oa[h][c] = 0.0f;
    float ls0 = 0.0f, ls1 = 0.0f;

    const float* mrow0 = mask + ((size_t)(b * NN) + i0 + r0) * NN + 2 * ql;
    const float* mrow1 = mrow0 + (size_t)8 * NN;

    const uint32_t* qb0 = Qh + r0 * QLDH + ql;
    const uint32_t* qb1 = Qh + (r0 + 8) * QLDH + ql;

#pragma unroll 1
    for (int jt = 0; jt < 64; jt++) {
        const int j0 = jt << 5;
        CP_WAIT0();
        __syncthreads();   // stage jt (K + V buf jt&1) visible

        // ---- issue V copy for jt+1 into other buffer (fully hidden) ----
        if (jt < 63) {
            const uint32_t vdst = smb +
                (uint32_t)(VT_OFF + ((jt + 1) & 1) * VT_STRIDE) * 4;
            const uint32_t* vn = vg2 + (size_t)((jt + 1) * 16) * HH;
#pragma unroll
            for (int t = 0; t < 2; t++) {
                const int idx = tid + t * 256;
                const int row = idx >> 5, c4 = idx & 31;
                CP_ASYNC16(vdst + (uint32_t)(row * 136 + c4 * 4) * 4,
                           vn + (size_t)row * HH + c4 * 4);
            }
            CP_COMMIT();
        }

        // ---- prefetch this stage's mask (hidden behind QK) ----
        float2 mh0[4], mh1[4];
#pragma unroll
        for (int nb = 0; nb < 4; nb++) {
            const int jcol = j0 + nb * 8;
            mh0[nb] = __ldg(reinterpret_cast<const float2*>(mrow0 + jcol));
            mh1[nb] = __ldg(reinterpret_cast<const float2*>(mrow1 + jcol));
        }

        // ---- S = Q K^T : fp16 m16n8k16, kk-outer (8 chunks of k=16) ----
        float sf[4][4];
#pragma unroll
        for (int nb = 0; nb < 4; nb++)
#pragma unroll
            for (int c = 0; c < 4; c++) sf[nb][c] = 0.0f;

#pragma unroll
        for (int kk = 0; kk < 8; kk++) {
            uint32_t qa[4];
            qa[0] = qb0[kk * 8];           // row r0,   h = 16kk+2ql,+1
            qa[1] = qb1[kk * 8];           // row r0+8
            qa[2] = qb0[kk * 8 + 4];       // row r0,   h = 16kk+8+2ql,+1
            qa[3] = qb1[kk * 8 + 4];
#pragma unroll
            for (int nb = 0; nb < 4; nb++) {
                const uint32_t* kb = Kh + (nb * 8 + qp) * QLDH + kk * 8 + ql;
                mma16n8k16h(sf[nb], qa, kb[0], kb[4]);
            }
        }

        __syncthreads();   // all warps done reading Kh
        if (jt < 63) {
            const uint32_t* kn = kg2 + (size_t)(j0 + 32) * 64;
#pragma unroll
            for (int t = 0; t < 2; t++) {
                const int idx = tid + t * 256;
                const int row = idx >> 4, c4 = idx & 15;
                CP_ASYNC16(smb + (uint32_t)(KS_OFF + row * QLDH + c4 * 4) * 4,
                           kn + (size_t)row * 64 + c4 * 4);
            }
            CP_COMMIT();
        }

        // ---- per nb-pair: mask + exp(s-10) + fp16 pack + PV (m16n8k16) ----
        const uint32_t* sVt = smw + VT_OFF + (jt & 1) * VT_STRIDE;
#pragma unroll
        for (int m = 0; m < 2; m++) {
            const int nE = 2 * m, nO = 2 * m + 1;
            float pE0 = (mh0[nE].x != 0.0f) ? __expf(sf[nE][0] - 10.0f) : 0.0f;
            float pE1 = (mh0[nE].y != 0.0f) ? __expf(sf[nE][1] - 10.0f) : 0.0f;
            float pE2 = (mh1[nE].x != 0.0f) ? __expf(sf[nE][2] - 10.0f) : 0.0f;
            float pE3 = (mh1[nE].y != 0.0f) ? __expf(sf[nE][3] - 10.0f) : 0.0f;
            float pO0 = (mh0[nO].x != 0.0f) ? __expf(sf[nO][0] - 10.0f) : 0.0f;
            float pO1 = (mh0[nO].y != 0.0f) ? __expf(sf[nO][1] - 10.0f) : 0.0f;
            float pO2 = (mh1[nO].x != 0.0f) ? __expf(sf[nO][2] - 10.0f) : 0.0f;
            float pO3 = (mh1[nO].y != 0.0f) ? __expf(sf[nO][3] - 10.0f) : 0.0f;
            ls0 += (pE0 + pE1) + (pO0 + pO1);
            ls1 += (pE2 + pE3) + (pO2 + pO3);
            uint32_t pa[4];
            pa[0] = h2pack(pE0, pE1);
            pa[1] = h2pack(pE2, pE3);
            pa[2] = h2pack(pO0, pO1);
            pa[3] = h2pack(pO2, pO3);

            const uint32_t* vb0 = sVt + (m * 8 + ql) * 136 + qp;
            const uint32_t* vb1 = sVt + (m * 8 + ql + 4) * 136 + qp;
#pragma unroll
            for (int h = 0; h < 16; h++) {
                mma16n8k16h(oa[h], pa, vb0[h * 8], vb1[h * 8]);
            }
        }
    }

    // ---- epilogue: quad reduction, normalize, store ----
    ls0 += __shfl_xor_sync(0xffffffffu, ls0, 1);
    ls0 += __shfl_xor_sync(0xffffffffu, ls0, 2);
    ls1 += __shfl_xor_sync(0xffffffffu, ls1, 1);
    ls1 += __shfl_xor_sync(0xffffffffu, ls1, 2);
    const float inv0 = 1.0f / ls0;
    const float inv1 = 1.0f / ls1;
    float* orow0 = out + ((size_t)(b * NN) + i0 + r0) * HH + 2 * ql;
    float* orow1 = orow0 + (size_t)8 * HH;
#pragma unroll
    for (int h = 0; h < 16; h++) {
        float2 v0, v1;
        v0.x = oa[h][0] * inv0; v0.y = oa[h][1] * inv0;
        v1.x = oa[h][2] * inv1; v1.y = oa[h][3] * inv1;
        *reinterpret_cast<float2*>(orow0 + h * 8) = v0;
        *reinterpret_cast<float2*>(orow1 + h * 8) = v1;
    }
}

extern "C" void kernel_launch(void* const* d_in, const int* in_sizes, int n_in,
                              void* d_out, int out_size) {
    const float* x    = (const float*)d_in[0];
    const float* mask = (const float*)d_in[1];
    const float* Wv   = (const float*)d_in[2];
    const float* bv   = (const float*)d_in[3];
    const float* Wk   = (const float*)d_in[4];
    const float* bk   = (const float*)d_in[5];
    const float* Wq   = (const float*)d_in[6];
    const float* bq   = (const float*)d_in[7];
    float* out = (float*)d_out;

    cudaFuncSetAttribute(proj_kernel, cudaFuncAttributeMaxDynamicSharedMemorySize,
                         49152);
    cudaFuncSetAttribute(attn_mma, cudaFuncAttributeMaxDynamicSharedMemorySize,
                         SMEM_ATT);

    proj_kernel<<<dim3(1024, 3, 1), 256, 49152>>>(x, Wq, bq, Wk, bk, Wv, bv);
    attn_mma<<<512, 256, SMEM_ATT>>>(mask, out);
}

// round 13
// speedup vs baseline: 1.6005x; 1.1625x over previous
#include <cuda_runtime.h>
#include <cuda_fp16.h>
#include <cstdint>
#include <cstddef>

#define BB 32
#define NN 2048
#define DD 128
#define HH 128

// Scratch (allocation-free rule: static device arrays).
// g_q/g_k: fp16x2 h-pair-packed uint32 [B*N][64].
// g_v:     fp16x2 j-pair-packed uint32 [B*1024][128].
__device__ float g_q[BB * NN * HH];
__device__ float g_k[BB * NN * HH];
__device__ float g_v[BB * NN * HH];

// pack two fp32 -> fp16x2 (lo = a, hi = b), saturating to finite
__device__ __forceinline__ uint32_t h2pack(float a, float b) {
    uint32_t r;
    asm("cvt.rn.satfinite.f16x2.f32 %0, %1, %2;" : "=r"(r) : "f"(b), "f"(a));
    return r;
}

// warp mma: D(16x8) += A(16x16,row,f16) * B(16x8,col,f16), fp32 accum
__device__ __forceinline__ void mma16n8k16h(float* c, const uint32_t* a,
                                            uint32_t b0, uint32_t b1) {
    asm volatile(
        "mma.sync.aligned.m16n8k16.row.col.f32.f16.f16.f32 "
        "{%0,%1,%2,%3}, {%4,%5,%6,%7}, {%8,%9}, {%0,%1,%2,%3};"
        : "+f"(c[0]), "+f"(c[1]), "+f"(c[2]), "+f"(c[3])
        : "r"(a[0]), "r"(a[1]), "r"(a[2]), "r"(a[3]), "r"(b0), "r"(b1));
}

__device__ __forceinline__ uint32_t smem_u32(const void* p) {
    uint32_t a;
    asm("{ .reg .u64 t; cvta.to.shared.u64 t, %1; cvt.u32.u64 %0, t; }"
        : "=r"(a) : "l"(p));
    return a;
}

#define CP_ASYNC16(dst, src)                                                \
    asm volatile("cp.async.cg.shared.global [%0], [%1], 16;" ::             \
                     "r"(dst), "l"(src) : "memory")
#define CP_COMMIT() asm volatile("cp.async.commit_group;" ::: "memory")
#define CP_WAIT0() asm volatile("cp.async.wait_group 0;" ::: "memory")
#define CP_WAIT1() asm volatile("cp.async.wait_group 1;" ::: "memory")

// ============================================================
// Kernel A: QKV projection via fp16 MMA with hi/lo error split.
//   y = tanh(x @ W + b);  x = xh + xl, W = Wh + Wl (fp16 splits)
//   y ~= xh@Wh + xh@Wl + xl@Wh  (dropped xl@Wl ~ 2^-22 -> fp32-faithful)
// CTA: 256 thr / 8 warps, 128-row tile; warp = 16 rows x 128 cols
// (fragment layouts identical to the attention kernel's Q/K paths).
// Outputs: q/k fp16x2 h-pair packed [row][64]; v fp16x2 j-pair packed.
// smem (u32 words): Xh[128][68] | Xl[128][68] | Wh[128][68] | Wl[128][68]
// ============================================================
#define PW 68
#define PX_H 0
#define PX_L 8704
#define PW_H 17408
#define PW_L 26112
#define SMEM_PROJ (34816 * 4)

__global__ __launch_bounds__(256, 1) void proj_kernel(
    const float* __restrict__ x,
    const float* __restrict__ Wq, const float* __restrict__ bq,
    const float* __restrict__ Wk, const float* __restrict__ bk,
    const float* __restrict__ Wv, const float* __restrict__ bv) {
    extern __shared__ uint32_t ps[];
    const int tid = threadIdx.x;
    const int lane = tid & 31;
    const int w = tid >> 5;
    const int qp = lane >> 2;
    const int ql = lane & 3;
    const int row0 = blockIdx.x * 128;

    const float* W;
    const float* bias;
    float* outp;
    bool isV = false;
    if (blockIdx.y == 0)      { W = Wq; bias = bq; outp = g_q; }
    else if (blockIdx.y == 1) { W = Wk; bias = bk; outp = g_k; }
    else                      { W = Wv; bias = bv; outp = g_v; isV = true; }

    // ---- load + split x tile (128 x 128 f32) ----
#pragma unroll
    for (int t = 0; t < 16; t++) {
        const int idx = tid + t * 256;       // 0..4095 float4s
        const int row = idx >> 5, c = idx & 31;
        float4 v = *reinterpret_cast<const float4*>(
            x + (size_t)(row0 + row) * DD + 4 * c);
        float rx = __half2float(__float2half_rn(v.x));
        float ry = __half2float(__float2half_rn(v.y));
        float rz = __half2float(__float2half_rn(v.z));
        float rw = __half2float(__float2half_rn(v.w));
        uint2 uh, ul;
        uh.x = h2pack(v.x, v.y);
        uh.y = h2pack(v.z, v.w);
        ul.x = h2pack(v.x - rx, v.y - ry);
        ul.y = h2pack(v.z - rz, v.w - rw);
        *reinterpret_cast<uint2*>(ps + PX_H + row * PW + 2 * c) = uh;
        *reinterpret_cast<uint2*>(ps + PX_L + row * PW + 2 * c) = ul;
    }
    // ---- load + split W transposed: Wt[n][kp] = (W[2kp][n], W[2kp+1][n]) ----
#pragma unroll
    for (int t = 0; t < 32; t++) {
        const int idx = tid + t * 256;       // 0..8191 words
        const int kp = idx >> 7, n = idx & 127;
        float a = __ldg(W + (size_t)(2 * kp) * HH + n);
        float b = __ldg(W + (size_t)(2 * kp + 1) * HH + n);
        float ra = __half2float(__float2half_rn(a));
        float rb = __half2float(__float2half_rn(b));
        ps[PW_H + n * PW + kp] = h2pack(a, b);
        ps[PW_L + n * PW + kp] = h2pack(a - ra, b - rb);
    }
    __syncthreads();

    // ---- 3-pass MMA: Xh*Wh + Xh*Wl + Xl*Wh ----
    float oacc[16][4];
#pragma unroll
    for (int nb = 0; nb < 16; nb++)
#pragma unroll
        for (int c = 0; c < 4; c++) oacc[nb][c] = 0.0f;

    const int r0 = w * 16 + qp;
    const uint32_t* a0h = ps + PX_H + r0 * PW + ql;
    const uint32_t* a0l = ps + PX_L + r0 * PW + ql;

#pragma unroll 1
    for (int pass = 0; pass < 3; pass++) {
        const uint32_t* A0 = (pass == 2) ? a0l : a0h;
        const uint32_t* A1 = A0 + 8 * PW;
        const uint32_t* Wb = ps + ((pass == 1) ? PW_L : PW_H);
#pragma unroll
        for (int kk = 0; kk < 8; kk++) {
            uint32_t qa[4];
            qa[0] = A0[kk * 8];
            qa[1] = A1[kk * 8];
            qa[2] = A0[kk * 8 + 4];
            qa[3] = A1[kk * 8 + 4];
#pragma unroll
            for (int nb = 0; nb < 16; nb++) {
                const uint32_t* kb = Wb + (nb * 8 + qp) * PW + kk * 8 + ql;
                mma16n8k16h(oacc[nb], qa, kb[0], kb[4]);
            }
        }
    }

    // ---- epilogue: bias + tanh + pack + store ----
#pragma unroll
    for (int nb = 0; nb < 16; nb++) {
        const int n0 = nb * 8 + 2 * ql;
        float2 bb = __ldg(reinterpret_cast<const float2*>(bias + n0));
        float t0 = tanhf(oacc[nb][0] + bb.x);
        float t1 = tanhf(oacc[nb][1] + bb.y);
        float t2 = tanhf(oacc[nb][2] + bb.x);
        float t3 = tanhf(oacc[nb][3] + bb.y);
        if (!isV) {
            uint32_t* o2 = reinterpret_cast<uint32_t*>(outp);
            o2[(size_t)(row0 + r0) * 64 + nb * 4 + ql] = h2pack(t0, t1);
            o2[(size_t)(row0 + r0 + 8) * 64 + nb * 4 + ql] = h2pack(t2, t3);
        } else {
            float s0 = __shfl_xor_sync(0xffffffffu, t0, 4);
            float s1 = __shfl_xor_sync(0xffffffffu, t1, 4);
            float s2 = __shfl_xor_sync(0xffffffffu, t2, 4);
            float s3 = __shfl_xor_sync(0xffffffffu, t3, 4);
            uint32_t* v2 = reinterpret_cast<uint32_t*>(g_v);
            if (!(qp & 1)) {
                const size_t jp = (size_t)(row0 + w * 16 + qp) >> 1;
                uint2 u;
                u.x = h2pack(t0, s0);   // lo = even row
                u.y = h2pack(t1, s1);
                *reinterpret_cast<uint2*>(v2 + jp * HH + nb * 8 + 2 * ql) = u;
            } else {
                const size_t jp = (size_t)(row0 + w * 16 + 8 + qp - 1) >> 1;
                uint2 u;
                u.x = h2pack(s2, t2);
                u.y = h2pack(s3, t3);
                *reinterpret_cast<uint2*>(v2 + jp * HH + nb * 8 + 2 * ql) = u;
            }
        }
    }
}

// ============================================================
// Kernel B: flash attention v11 — all-fp16 MMA, TRIPLE-buffered K/V,
// ONE __syncthreads per stage (stage jt+2 copies issued right after the
// top-of-stage sync; that buffer was last read in stage jt-1).
// smem (words): Qh[128][68] | Kh 3x[32][68] | Vt 3x[16][136]
// ============================================================
#define QLDH 68
#define KS_OFF (128 * QLDH)
#define KSTRIDE (32 * QLDH)
#define VT_OFF (KS_OFF + 3 * KSTRIDE)
#define VSTRIDE (16 * 136)
#define SMEM_ATT ((VT_OFF + 3 * VSTRIDE) * 4)

__device__ __forceinline__ void attn_stage_copy(uint32_t smb, int s,
                                                const uint32_t* kg2,
                                                const uint32_t* vg2, int tid) {
    const int buf = s % 3;
    const uint32_t kdst = smb + (uint32_t)(KS_OFF + buf * KSTRIDE) * 4;
    const uint32_t vdst = smb + (uint32_t)(VT_OFF + buf * VSTRIDE) * 4;
    const uint32_t* kn = kg2 + (size_t)(s * 32) * 64;
    const uint32_t* vn = vg2 + (size_t)(s * 16) * HH;
#pragma unroll
    for (int t = 0; t < 2; t++) {
        const int idx = tid + t * 256;       // 0..511
        const int krow = idx >> 4, kc = idx & 15;
        CP_ASYNC16(kdst + (uint32_t)(krow * QLDH + kc * 4) * 4,
                   kn + (size_t)krow * 64 + kc * 4);
        const int vrow = idx >> 5, vc = idx & 31;
        CP_ASYNC16(vdst + (uint32_t)(vrow * 136 + vc * 4) * 4,
                   vn + (size_t)vrow * HH + vc * 4);
    }
}

__global__ __launch_bounds__(256, 2) void attn_mma(
    const float* __restrict__ mask, float* __restrict__ out) {
    extern __shared__ uint32_t smw[];
    uint32_t* Qh = smw;
    const uint32_t smb = smem_u32(smw);

    const int tid = threadIdx.x;
    const int lane = tid & 31;
    const int w = tid >> 5;
    const int b = blockIdx.x >> 4;
    const int i0 = (blockIdx.x & 15) << 7;
    const int qp = lane >> 2;
    const int ql = lane & 3;
    const int r0 = w * 16 + qp;

    const uint32_t* qg2 =
        reinterpret_cast<const uint32_t*>(g_q) + ((size_t)(b * NN) + i0) * 64;
    const uint32_t* kg2 =
        reinterpret_cast<const uint32_t*>(g_k) + (size_t)(b * NN) * 64;
    const uint32_t* vg2 =
        reinterpret_cast<const uint32_t*>(g_v) + (size_t)b * 1024 * HH;

    // ---- prologue: Q + stage0 (group), stage1 (group) ----
#pragma unroll
    for (int t = 0; t < 8; t++) {
        const int idx = tid + t * 256;       // 0..2047 16B chunks of Q
        const int row = idx >> 4, c4 = idx & 15;
        CP_ASYNC16(smb + (uint32_t)(row * QLDH + c4 * 4) * 4,
                   qg2 + (size_t)row * 64 + c4 * 4);
    }
    attn_stage_copy(smb, 0, kg2, vg2, tid);
    CP_COMMIT();
    attn_stage_copy(smb, 1, kg2, vg2, tid);
    CP_COMMIT();

    float oa[16][4];
#pragma unroll
    for (int h = 0; h < 16; h++)
#pragma unroll
        for (int c = 0; c < 4; c++) oa[h][c] = 0.0f;
    float ls0 = 0.0f, ls1 = 0.0f;

    const float* mrow0 = mask + ((size_t)(b * NN) + i0 + r0) * NN + 2 * ql;
    const float* mrow1 = mrow0 + (size_t)8 * NN;

    const uint32_t* qb0 = Qh + r0 * QLDH + ql;
    const uint32_t* qb1 = Qh + (r0 + 8) * QLDH + ql;

#pragma unroll 1
    for (int jt = 0; jt < 64; jt++) {
        const int j0 = jt << 5;
        if (jt < 63) { CP_WAIT1(); } else { CP_WAIT0(); }
        __syncthreads();   // stage jt resident; all warps done with jt-1

        if (jt < 62) {
            attn_stage_copy(smb, jt + 2, kg2, vg2, tid);
            CP_COMMIT();
        }

        const uint32_t* Kh = smw + KS_OFF + (jt % 3) * KSTRIDE;
        const uint32_t* sVt = smw + VT_OFF + (jt % 3) * VSTRIDE;

        // ---- prefetch this stage's mask (hidden behind QK) ----
        float2 mh0[4], mh1[4];
#pragma unroll
        for (int nb = 0; nb < 4; nb++) {
            const int jcol = j0 + nb * 8;
            mh0[nb] = __ldg(reinterpret_cast<const float2*>(mrow0 + jcol));
            mh1[nb] = __ldg(reinterpret_cast<const float2*>(mrow1 + jcol));
        }

        // ---- S = Q K^T : fp16 m16n8k16 ----
        float sf[4][4];
#pragma unroll
        for (int nb = 0; nb < 4; nb++)
#pragma unroll
            for (int c = 0; c < 4; c++) sf[nb][c] = 0.0f;

#pragma unroll
        for (int kk = 0; kk < 8; kk++) {
            uint32_t qa[4];
            qa[0] = qb0[kk * 8];
            qa[1] = qb1[kk * 8];
            qa[2] = qb0[kk * 8 + 4];
            qa[3] = qb1[kk * 8 + 4];
#pragma unroll
            for (int nb = 0; nb < 4; nb++) {
                const uint32_t* kb = Kh + (nb * 8 + qp) * QLDH + kk * 8 + ql;
                mma16n8k16h(sf[nb], qa, kb[0], kb[4]);
            }
        }

        // ---- per nb-pair: mask + exp(s-10) + fp16 pack + PV ----
#pragma unroll
        for (int m = 0; m < 2; m++) {
            const int nE = 2 * m, nO = 2 * m + 1;
            float pE0 = (mh0[nE].x != 0.0f) ? __expf(sf[nE][0] - 10.0f) : 0.0f;
            float pE1 = (mh0[nE].y != 0.0f) ? __expf(sf[nE][1] - 10.0f) : 0.0f;
            float pE2 = (mh1[nE].x != 0.0f) ? __expf(sf[nE][2] - 10.0f) : 0.0f;
            float pE3 = (mh1[nE].y != 0.0f) ? __expf(sf[nE][3] - 10.0f) : 0.0f;
            float pO0 = (mh0[nO].x != 0.0f) ? __expf(sf[nO][0] - 10.0f) : 0.0f;
            float pO1 = (mh0[nO].y != 0.0f) ? __expf(sf[nO][1] - 10.0f) : 0.0f;
            float pO2 = (mh1[nO].x != 0.0f) ? __expf(sf[nO][2] - 10.0f) : 0.0f;
            float pO3 = (mh1[nO].y != 0.0f) ? __expf(sf[nO][3] - 10.0f) : 0.0f;
            ls0 += (pE0 + pE1) + (pO0 + pO1);
            ls1 += (pE2 + pE3) + (pO2 + pO3);
            uint32_t pa[4];
            pa[0] = h2pack(pE0, pE1);
            pa[1] = h2pack(pE2, pE3);
            pa[2] = h2pack(pO0, pO1);
            pa[3] = h2pack(pO2, pO3);

            const uint32_t* vb0 = sVt + (m * 8 + ql) * 136 + qp;
            const uint32_t* vb1 = sVt + (m * 8 + ql + 4) * 136 + qp;
#pragma unroll
            for (int h = 0; h < 16; h++) {
                mma16n8k16h(oa[h], pa, vb0[h * 8], vb1[h * 8]);
            }
        }
    }

    // ---- epilogue: quad reduction, normalize, store ----
    ls0 += __shfl_xor_sync(0xffffffffu, ls0, 1);
    ls0 += __shfl_xor_sync(0xffffffffu, ls0, 2);
    ls1 += __shfl_xor_sync(0xffffffffu, ls1, 1);
    ls1 += __shfl_xor_sync(0xffffffffu, ls1, 2);
    const float inv0 = 1.0f / ls0;
    const float inv1 = 1.0f / ls1;
    float* orow0 = out + ((size_t)(b * NN) + i0 + r0) * HH + 2 * ql;
    float* orow1 = orow0 + (size_t)8 * HH;
#pragma unroll
    for (int h = 0; h < 16; h++) {
        float2 v0, v1;
        v0.x = oa[h][0] * inv0; v0.y = oa[h][1] * inv0;
        v1.x = oa[h][2] * inv1; v1.y = oa[h][3] * inv1;
        *reinterpret_cast<float2*>(orow0 + h * 8) = v0;
        *reinterpret_cast<float2*>(orow1 + h * 8) = v1;
    }
}

extern "C" void kernel_launch(void* const* d_in, const int* in_sizes, int n_in,
                              void* d_out, int out_size) {
    const float* x    = (const float*)d_in[0];
    const float* mask = (const float*)d_in[1];
    const float* Wv   = (const float*)d_in[2];
    const float* bv   = (const float*)d_in[3];
    const float* Wk   = (const float*)d_in[4];
    const float* bk   = (const float*)d_in[5];
    const float* Wq   = (const float*)d_in[6];
    const float* bq   = (const float*)d_in[7];
    float* out = (float*)d_out;

    cudaFuncSetAttribute(proj_kernel, cudaFuncAttributeMaxDynamicSharedMemorySize,
                         SMEM_PROJ);
    cudaFuncSetAttribute(attn_mma, cudaFuncAttributeMaxDynamicSharedMemorySize,
                         SMEM_ATT);

    proj_kernel<<<dim3(512, 3, 1), 256, SMEM_PROJ>>>(x, Wq, bq, Wk, bk, Wv, bv);
    attn_mma<<<512, 256, SMEM_ATT>>>(mask, out);
}

// round 14
// speedup vs baseline: 1.6568x; 1.0352x over previous
#include <cuda_runtime.h>
#include <cuda_fp16.h>
#include <cstdint>
#include <cstddef>

#define BB 32
#define NN 2048
#define DD 128
#define HH 128

// Scratch (allocation-free rule: static device arrays).
// g_q/g_k: fp16x2 h-pair-packed uint32 [B*N][64].
// g_v:     fp16x2 j-pair-packed uint32 [B*1024][128].
__device__ float g_q[BB * NN * HH];
__device__ float g_k[BB * NN * HH];
__device__ float g_v[BB * NN * HH];

// pack two fp32 -> fp16x2 (lo = a, hi = b), saturating to finite
__device__ __forceinline__ uint32_t h2pack(float a, float b) {
    uint32_t r;
    asm("cvt.rn.satfinite.f16x2.f32 %0, %1, %2;" : "=r"(r) : "f"(b), "f"(a));
    return r;
}
__device__ __forceinline__ float tanha(float x) {
    float r;
    asm("tanh.approx.f32 %0, %1;" : "=f"(r) : "f"(x));
    return r;
}

// warp mma: D(16x8) += A(16x16,row,f16) * B(16x8,col,f16), fp32 accum
__device__ __forceinline__ void mma16n8k16h(float* c, const uint32_t* a,
                                            uint32_t b0, uint32_t b1) {
    asm volatile(
        "mma.sync.aligned.m16n8k16.row.col.f32.f16.f16.f32 "
        "{%0,%1,%2,%3}, {%4,%5,%6,%7}, {%8,%9}, {%0,%1,%2,%3};"
        : "+f"(c[0]), "+f"(c[1]), "+f"(c[2]), "+f"(c[3])
        : "r"(a[0]), "r"(a[1]), "r"(a[2]), "r"(a[3]), "r"(b0), "r"(b1));
}

__device__ __forceinline__ uint32_t smem_u32(const void* p) {
    uint32_t a;
    asm("{ .reg .u64 t; cvta.to.shared.u64 t, %1; cvt.u32.u64 %0, t; }"
        : "=r"(a) : "l"(p));
    return a;
}

#define CP_ASYNC16(dst, src)                                                \
    asm volatile("cp.async.cg.shared.global [%0], [%1], 16;" ::             \
                     "r"(dst), "l"(src) : "memory")
#define CP_COMMIT() asm volatile("cp.async.commit_group;" ::: "memory")
#define CP_WAIT0() asm volatile("cp.async.wait_group 0;" ::: "memory")
#define CP_WAIT1() asm volatile("cp.async.wait_group 1;" ::: "memory")

// ============================================================
// Kernel A: QKV projection via fp16 MMA with hi/lo error split.
//   y = tanh(x @ W + b);  y ~= xh@Wh + xh@Wl + xl@Wh  (fp32-faithful)
// tanh via tanh.approx.f32 (error ~2^-11, same order as fp16 storage).
// Outputs: q/k fp16x2 h-pair packed [row][64]; v fp16x2 j-pair packed.
// smem (u32 words): Xh[128][68] | Xl[128][68] | Wh[128][68] | Wl[128][68]
// ============================================================
#define PW 68
#define PX_H 0
#define PX_L 8704
#define PW_H 17408
#define PW_L 26112
#define SMEM_PROJ (34816 * 4)

__global__ __launch_bounds__(256, 1) void proj_kernel(
    const float* __restrict__ x,
    const float* __restrict__ Wq, const float* __restrict__ bq,
    const float* __restrict__ Wk, const float* __restrict__ bk,
    const float* __restrict__ Wv, const float* __restrict__ bv) {
    extern __shared__ uint32_t ps[];
    const int tid = threadIdx.x;
    const int lane = tid & 31;
    const int w = tid >> 5;
    const int qp = lane >> 2;
    const int ql = lane & 3;
    const int row0 = blockIdx.x * 128;

    const float* W;
    const float* bias;
    float* outp;
    bool isV = false;
    if (blockIdx.y == 0)      { W = Wq; bias = bq; outp = g_q; }
    else if (blockIdx.y == 1) { W = Wk; bias = bk; outp = g_k; }
    else                      { W = Wv; bias = bv; outp = g_v; isV = true; }

    // ---- load + split x tile (128 x 128 f32) ----
#pragma unroll
    for (int t = 0; t < 16; t++) {
        const int idx = tid + t * 256;       // 0..4095 float4s
        const int row = idx >> 5, c = idx & 31;
        float4 v = *reinterpret_cast<const float4*>(
            x + (size_t)(row0 + row) * DD + 4 * c);
        float rx = __half2float(__float2half_rn(v.x));
        float ry = __half2float(__float2half_rn(v.y));
        float rz = __half2float(__float2half_rn(v.z));
        float rw = __half2float(__float2half_rn(v.w));
        uint2 uh, ul;
        uh.x = h2pack(v.x, v.y);
        uh.y = h2pack(v.z, v.w);
        ul.x = h2pack(v.x - rx, v.y - ry);
        ul.y = h2pack(v.z - rz, v.w - rw);
        *reinterpret_cast<uint2*>(ps + PX_H + row * PW + 2 * c) = uh;
        *reinterpret_cast<uint2*>(ps + PX_L + row * PW + 2 * c) = ul;
    }
    // ---- load + split W transposed: Wt[n][kp] = (W[2kp][n], W[2kp+1][n]) ----
#pragma unroll
    for (int t = 0; t < 32; t++) {
        const int idx = tid + t * 256;       // 0..8191 words
        const int kp = idx >> 7, n = idx & 127;
        float a = __ldg(W + (size_t)(2 * kp) * HH + n);
        float b = __ldg(W + (size_t)(2 * kp + 1) * HH + n);
        float ra = __half2float(__float2half_rn(a));
        float rb = __half2float(__float2half_rn(b));
        ps[PW_H + n * PW + kp] = h2pack(a, b);
        ps[PW_L + n * PW + kp] = h2pack(a - ra, b - rb);
    }
    __syncthreads();

    // ---- 3-pass MMA: Xh*Wh + Xh*Wl + Xl*Wh ----
    float oacc[16][4];
#pragma unroll
    for (int nb = 0; nb < 16; nb++)
#pragma unroll
        for (int c = 0; c < 4; c++) oacc[nb][c] = 0.0f;

    const int r0 = w * 16 + qp;
    const uint32_t* a0h = ps + PX_H + r0 * PW + ql;
    const uint32_t* a0l = ps + PX_L + r0 * PW + ql;

#pragma unroll 1
    for (int pass = 0; pass < 3; pass++) {
        const uint32_t* A0 = (pass == 2) ? a0l : a0h;
        const uint32_t* A1 = A0 + 8 * PW;
        const uint32_t* Wb = ps + ((pass == 1) ? PW_L : PW_H);
#pragma unroll
        for (int kk = 0; kk < 8; kk++) {
            uint32_t qa[4];
            qa[0] = A0[kk * 8];
            qa[1] = A1[kk * 8];
            qa[2] = A0[kk * 8 + 4];
            qa[3] = A1[kk * 8 + 4];
#pragma unroll
            for (int nb = 0; nb < 16; nb++) {
                const uint32_t* kb = Wb + (nb * 8 + qp) * PW + kk * 8 + ql;
                mma16n8k16h(oacc[nb], qa, kb[0], kb[4]);
            }
        }
    }

    // ---- epilogue: bias + tanh.approx + pack + store ----
#pragma unroll
    for (int nb = 0; nb < 16; nb++) {
        const int n0 = nb * 8 + 2 * ql;
        float2 bb = __ldg(reinterpret_cast<const float2*>(bias + n0));
        float t0 = tanha(oacc[nb][0] + bb.x);
        float t1 = tanha(oacc[nb][1] + bb.y);
        float t2 = tanha(oacc[nb][2] + bb.x);
        float t3 = tanha(oacc[nb][3] + bb.y);
        if (!isV) {
            uint32_t* o2 = reinterpret_cast<uint32_t*>(outp);
            o2[(size_t)(row0 + r0) * 64 + nb * 4 + ql] = h2pack(t0, t1);
            o2[(size_t)(row0 + r0 + 8) * 64 + nb * 4 + ql] = h2pack(t2, t3);
        } else {
            float s0 = __shfl_xor_sync(0xffffffffu, t0, 4);
            float s1 = __shfl_xor_sync(0xffffffffu, t1, 4);
            float s2 = __shfl_xor_sync(0xffffffffu, t2, 4);
            float s3 = __shfl_xor_sync(0xffffffffu, t3, 4);
            uint32_t* v2 = reinterpret_cast<uint32_t*>(g_v);
            if (!(qp & 1)) {
                const size_t jp = (size_t)(row0 + w * 16 + qp) >> 1;
                uint2 u;
                u.x = h2pack(t0, s0);
                u.y = h2pack(t1, s1);
                *reinterpret_cast<uint2*>(v2 + jp * HH + nb * 8 + 2 * ql) = u;
            } else {
                const size_t jp = (size_t)(row0 + w * 16 + 8 + qp - 1) >> 1;
                uint2 u;
                u.x = h2pack(s2, t2);
                u.y = h2pack(s3, t3);
                *reinterpret_cast<uint2*>(v2 + jp * HH + nb * 8 + 2 * ql) = u;
            }
        }
    }
}

// ============================================================
// Kernel B: flash attention v12.
//  - Q fragments PERSISTENT IN REGISTERS (fp16, 32 regs; no Q smem at all)
//  - mask flows through the cp.async triple-buffer pipeline (no mask regs
//    at QK time, no exposed mask DRAM latency)
//  - K/V/mask triple-buffered, ONE __syncthreads per stage
// smem (words): Kh 3x[32][68] | Vt 3x[16][136] | M 3x[128][36] = 105 KB
// ============================================================
#define QLDH 68
#define KSTRIDE (32 * QLDH)
#define VT_OFF (3 * KSTRIDE)
#define VSTRIDE (16 * 136)
#define MS_OFF (VT_OFF + 3 * VSTRIDE)
#define MPAD 36
#define MSTRIDE (128 * MPAD)
#define SMEM_ATT ((MS_OFF + 3 * MSTRIDE) * 4)

__device__ __forceinline__ void attn_stage_copy(uint32_t smb, int s,
                                                const uint32_t* kg2,
                                                const uint32_t* vg2,
                                                const float* mbase, int tid) {
    const int buf = s % 3;
    const uint32_t kdst = smb + (uint32_t)(buf * KSTRIDE) * 4;
    const uint32_t vdst = smb + (uint32_t)(VT_OFF + buf * VSTRIDE) * 4;
    const uint32_t mdst = smb + (uint32_t)(MS_OFF + buf * MSTRIDE) * 4;
    const uint32_t* kn = kg2 + (size_t)(s * 32) * 64;
    const uint32_t* vn = vg2 + (size_t)(s * 16) * HH;
    const float* mn = mbase + s * 32;
#pragma unroll
    for (int t = 0; t < 2; t++) {
        const int idx = tid + t * 256;       // 0..511
        const int krow = idx >> 4, kc = idx & 15;
        CP_ASYNC16(kdst + (uint32_t)(krow * QLDH + kc * 4) * 4,
                   kn + (size_t)krow * 64 + kc * 4);
        const int vrow = idx >> 5, vc = idx & 31;
        CP_ASYNC16(vdst + (uint32_t)(vrow * 136 + vc * 4) * 4,
                   vn + (size_t)vrow * HH + vc * 4);
    }
#pragma unroll
    for (int t = 0; t < 4; t++) {
        const int idx = tid + t * 256;       // 0..1023
        const int mrow = idx >> 3, mc = idx & 7;
        CP_ASYNC16(mdst + (uint32_t)(mrow * MPAD + mc * 4) * 4,
                   mn + (size_t)mrow * NN + mc * 4);
    }
}

__global__ __launch_bounds__(256, 2) void attn_mma(
    const float* __restrict__ mask, float* __restrict__ out) {
    extern __shared__ uint32_t smw[];
    const uint32_t smb = smem_u32(smw);

    const int tid = threadIdx.x;
    const int lane = tid & 31;
    const int w = tid >> 5;
    const int b = blockIdx.x >> 4;
    const int i0 = (blockIdx.x & 15) << 7;
    const int qp = lane >> 2;
    const int ql = lane & 3;
    const int r0 = w * 16 + qp;

    const uint32_t* qg2 =
        reinterpret_cast<const uint32_t*>(g_q) + ((size_t)(b * NN) + i0) * 64;
    const uint32_t* kg2 =
        reinterpret_cast<const uint32_t*>(g_k) + (size_t)(b * NN) * 64;
    const uint32_t* vg2 =
        reinterpret_cast<const uint32_t*>(g_v) + (size_t)b * 1024 * HH;
    const float* mbase = mask + ((size_t)(b * NN) + i0) * NN;

    // ---- prologue: stage0, stage1 copies in flight ----
    attn_stage_copy(smb, 0, kg2, vg2, mbase, tid);
    CP_COMMIT();
    attn_stage_copy(smb, 1, kg2, vg2, mbase, tid);
    CP_COMMIT();

    // ---- persistent Q fragments in registers (fp16-packed, one-time) ----
    uint32_t qa_all[8][4];
    {
        const uint32_t* q0 = qg2 + (size_t)r0 * 64 + ql;
        const uint32_t* q1 = qg2 + (size_t)(r0 + 8) * 64 + ql;
#pragma unroll
        for (int kk = 0; kk < 8; kk++) {
            qa_all[kk][0] = __ldg(q0 + kk * 8);
            qa_all[kk][1] = __ldg(q1 + kk * 8);
            qa_all[kk][2] = __ldg(q0 + kk * 8 + 4);
            qa_all[kk][3] = __ldg(q1 + kk * 8 + 4);
        }
    }

    float oa[16][4];
#pragma unroll
    for (int h = 0; h < 16; h++)
#pragma unroll
        for (int c = 0; c < 4; c++) oa[h][c] = 0.0f;
    float ls0 = 0.0f, ls1 = 0.0f;

#pragma unroll 1
    for (int jt = 0; jt < 64; jt++) {
        if (jt < 63) { CP_WAIT1(); } else { CP_WAIT0(); }
        __syncthreads();   // stage jt resident; all warps done with jt-1

        if (jt < 62) {
            attn_stage_copy(smb, jt + 2, kg2, vg2, mbase, tid);
            CP_COMMIT();
        }

        const uint32_t* Kh = smw + (jt % 3) * KSTRIDE;
        const uint32_t* sVt = smw + VT_OFF + (jt % 3) * VSTRIDE;
        const float* sM =
            reinterpret_cast<const float*>(smw + MS_OFF + (jt % 3) * MSTRIDE);

        // ---- S = Q K^T : fp16 m16n8k16, Q from registers ----
        float sf[4][4];
#pragma unroll
        for (int nb = 0; nb < 4; nb++)
#pragma unroll
            for (int c = 0; c < 4; c++) sf[nb][c] = 0.0f;

#pragma unroll
        for (int kk = 0; kk < 8; kk++) {
#pragma unroll
            for (int nb = 0; nb < 4; nb++) {
                const uint32_t* kb = Kh + (nb * 8 + qp) * QLDH + kk * 8 + ql;
                mma16n8k16h(sf[nb], qa_all[kk], kb[0], kb[4]);
            }
        }

        // ---- per nb-pair: mask (smem) + exp(s-10) + fp16 pack + PV ----
#pragma unroll
        for (int m = 0; m < 2; m++) {
            const int nE = 2 * m, nO = 2 * m + 1;
            float2 mE0 = *reinterpret_cast<const float2*>(
                sM + r0 * MPAD + nE * 8 + 2 * ql);
            float2 mE1 = *reinterpret_cast<const float2*>(
                sM + (r0 + 8) * MPAD + nE * 8 + 2 * ql);
            float2 mO0 = *reinterpret_cast<const float2*>(
                sM + r0 * MPAD + nO * 8 + 2 * ql);
            float2 mO1 = *reinterpret_cast<const float2*>(
                sM + (r0 + 8) * MPAD + nO * 8 + 2 * ql);
            float pE0 = (mE0.x != 0.0f) ? __expf(sf[nE][0] - 10.0f) : 0.0f;
            float pE1 = (mE0.y != 0.0f) ? __expf(sf[nE][1] - 10.0f) : 0.0f;
            float pE2 = (mE1.x != 0.0f) ? __expf(sf[nE][2] - 10.0f) : 0.0f;
            float pE3 = (mE1.y != 0.0f) ? __expf(sf[nE][3] - 10.0f) : 0.0f;
            float pO0 = (mO0.x != 0.0f) ? __expf(sf[nO][0] - 10.0f) : 0.0f;
            float pO1 = (mO0.y != 0.0f) ? __expf(sf[nO][1] - 10.0f) : 0.0f;
            float pO2 = (mO1.x != 0.0f) ? __expf(sf[nO][2] - 10.0f) : 0.0f;
            float pO3 = (mO1.y != 0.0f) ? __expf(sf[nO][3] - 10.0f) : 0.0f;
            ls0 += (pE0 + pE1) + (pO0 + pO1);
            ls1 += (pE2 + pE3) + (pO2 + pO3);
            uint32_t pa[4];
            pa[0] = h2pack(pE0, pE1);
            pa[1] = h2pack(pE2, pE3);
            pa[2] = h2pack(pO0, pO1);
            pa[3] = h2pack(pO2, pO3);

            const uint32_t* vb0 = sVt + (m * 8 + ql) * 136 + qp;
            const uint32_t* vb1 = sVt + (m * 8 + ql + 4) * 136 + qp;
#pragma unroll
            for (int h = 0; h < 16; h++) {
                mma16n8k16h(oa[h], pa, vb0[h * 8], vb1[h * 8]);
            }
        }
    }

    // ---- epilogue: quad reduction, normalize, store ----
    ls0 += __shfl_xor_sync(0xffffffffu, ls0, 1);
    ls0 += __shfl_xor_sync(0xffffffffu, ls0, 2);
    ls1 += __shfl_xor_sync(0xffffffffu, ls1, 1);
    ls1 += __shfl_xor_sync(0xffffffffu, ls1, 2);
    const float inv0 = 1.0f / ls0;
    const float inv1 = 1.0f / ls1;
    float* orow0 = out + ((size_t)(b * NN) + i0 + r0) * HH + 2 * ql;
    float* orow1 = orow0 + (size_t)8 * HH;
#pragma unroll
    for (int h = 0; h < 16; h++) {
        float2 v0, v1;
        v0.x = oa[h][0] * inv0; v0.y = oa[h][1] * inv0;
        v1.x = oa[h][2] * inv1; v1.y = oa[h][3] * inv1;
        *reinterpret_cast<float2*>(orow0 + h * 8) = v0;
        *reinterpret_cast<float2*>(orow1 + h * 8) = v1;
    }
}

extern "C" void kernel_launch(void* const* d_in, const int* in_sizes, int n_in,
                              void* d_out, int out_size) {
    const float* x    = (const float*)d_in[0];
    const float* mask = (const float*)d_in[1];
    const float* Wv   = (const float*)d_in[2];
    const float* bv   = (const float*)d_in[3];
    const float* Wk   = (const float*)d_in[4];
    const float* bk   = (const float*)d_in[5];
    const float* Wq   = (const float*)d_in[6];
    const float* bq   = (const float*)d_in[7];
    float* out = (float*)d_out;

    cudaFuncSetAttribute(proj_kernel, cudaFuncAttributeMaxDynamicSharedMemorySize,
                         SMEM_PROJ);
    cudaFuncSetAttribute(attn_mma, cudaFuncAttributeMaxDynamicSharedMemorySize,
                         SMEM_ATT);

    proj_kernel<<<dim3(512, 3, 1), 256, SMEM_PROJ>>>(x, Wq, bq, Wk, bk, Wv, bv);
    attn_mma<<<512, 256, SMEM_ATT>>>(mask, out);
}